// round 15
// baseline (speedup 1.0000x reference)
#include <cuda_runtime.h>
#include <cuda_fp16.h>
#include <cstdint>

// ---------------- problem constants ----------------
#define NW    4096
#define NTOK  64
#define CDIM  512
#define HEADS 16
#define DHEAD 32
#define MROWS (NW * NTOK)        // 262144
#define NQKV  (3 * CDIM)         // 1536

// ---------------- scratch (device globals; no allocs allowed) ----------------
__device__ __half g_xh  [(size_t)MROWS * CDIM];   // 256 MB  x in fp16
__device__ __half g_qkvh[(size_t)MROWS * NQKV];   // 768 MB  qkv in fp16
__device__ __half g_atth[(size_t)MROWS * CDIM];   // 256 MB  attn out in fp16
__device__ __half g_wqkv[(size_t)NQKV * CDIM];    // 1.5 MB  qkv_w^T fp16 [n][k]
__device__ __half g_wprj[(size_t)CDIM * CDIM];    // 0.5 MB  proj_w^T fp16 [n][k]
__device__ float  g_bias[HEADS * NTOK * NTOK];    // 256 KB

// ---------------- helpers ----------------
__device__ __forceinline__ void mma_tf32(float d[4],
                                         uint32_t a0, uint32_t a1, uint32_t a2, uint32_t a3,
                                         uint32_t b0, uint32_t b1) {
    asm volatile(
        "mma.sync.aligned.m16n8k8.row.col.f32.tf32.tf32.f32 "
        "{%0,%1,%2,%3}, {%4,%5,%6,%7}, {%8,%9}, {%0,%1,%2,%3};\n"
        : "+f"(d[0]), "+f"(d[1]), "+f"(d[2]), "+f"(d[3])
        : "r"(a0), "r"(a1), "r"(a2), "r"(a3), "r"(b0), "r"(b1));
}
__device__ __forceinline__ void mma_f16(float d[4],
                                        uint32_t a0, uint32_t a1, uint32_t a2, uint32_t a3,
                                        uint32_t b0, uint32_t b1) {
    asm volatile(
        "mma.sync.aligned.m16n8k16.row.col.f32.f16.f16.f32 "
        "{%0,%1,%2,%3}, {%4,%5,%6,%7}, {%8,%9}, {%0,%1,%2,%3};\n"
        : "+f"(d[0]), "+f"(d[1]), "+f"(d[2]), "+f"(d[3])
        : "r"(a0), "r"(a1), "r"(a2), "r"(a3), "r"(b0), "r"(b1));
}
__device__ __forceinline__ void ldsm_x4(uint32_t& r0, uint32_t& r1, uint32_t& r2, uint32_t& r3,
                                        uint32_t addr) {
    asm volatile("ldmatrix.sync.aligned.m8n8.x4.shared.b16 {%0,%1,%2,%3}, [%4];"
                 : "=r"(r0), "=r"(r1), "=r"(r2), "=r"(r3) : "r"(addr));
}
__device__ __forceinline__ uint32_t f2tf32(float x) {
    uint32_t r;
    asm("cvt.rna.tf32.f32 %0, %1;" : "=r"(r) : "f"(x));
    return r;
}
__device__ __forceinline__ uint32_t smem_u32(const void* p) {
    uint32_t a;
    asm("{ .reg .u64 t; cvta.to.shared.u64 t, %1; cvt.u32.u64 %0, t; }" : "=r"(a) : "l"(p));
    return a;
}
__device__ __forceinline__ void cp16(uint32_t dst, const void* src) {
    asm volatile("cp.async.cg.shared.global [%0], [%1], 16;\n" :: "r"(dst), "l"(src));
}
#define CP_COMMIT() asm volatile("cp.async.commit_group;\n" ::: "memory")
#define CP_WAIT1()  asm volatile("cp.async.wait_group 1;\n" ::: "memory")

// ---------------- prep: x fp32 -> fp16 ----------------
__global__ void cvt_half_kernel(const float* __restrict__ in, __half* __restrict__ out) {
    const size_t base = ((size_t)blockIdx.x * blockDim.x + threadIdx.x) * 8;
    float4 a = *(const float4*)(in + base);
    float4 b = *(const float4*)(in + base + 4);
    __half2 h0 = __floats2half2_rn(a.x, a.y);
    __half2 h1 = __floats2half2_rn(a.z, a.w);
    __half2 h2 = __floats2half2_rn(b.x, b.y);
    __half2 h3 = __floats2half2_rn(b.z, b.w);
    uint4 o;
    o.x = *(uint32_t*)&h0; o.y = *(uint32_t*)&h1;
    o.z = *(uint32_t*)&h2; o.w = *(uint32_t*)&h3;
    *(uint4*)(out + base) = o;
}

// ---------------- prep: W[k][n] fp32 -> Wt[n][k] fp16 ----------------
__global__ void wtrans_kernel(const float* __restrict__ w, __half* __restrict__ wt, int N) {
    const int idx = blockIdx.x * blockDim.x + threadIdx.x;  // over N*512
    const int n = idx >> 9;
    const int k = idx & 511;
    wt[idx] = __float2half_rn(w[(size_t)k * N + n]);
}

// ---------------- bias precompute: g_bias[h][i][j] = table[rel_index[i][j]][h] ----------------
__global__ void bias_kernel(const float* __restrict__ table,
                            const int* __restrict__ relidx,
                            float* __restrict__ bias_out) {
    int h = blockIdx.x;
    for (int idx = threadIdx.x; idx < NTOK * NTOK; idx += blockDim.x) {
        bias_out[h * (NTOK * NTOK) + idx] = table[relidx[idx] * HEADS + h];
    }
}

// ---------------- fp16 GEMM: C[M,N] = Xh[M,512] @ Wt[N,512]^T + bias[N] ----------------
// CTA 128x64, 8 warps 4(M)x2(N), warp tile 32x32 (acc=32 regs -> 3 CTAs/SM = 24 warps/SM).
// 3-stage cp.async, BK=32, fp16 SMEM pitch 80B, ldmatrix fragments.
#define BM 128
#define BN 64
#define BK 32
#define PITCH 80                          // bytes per row (64B data + 16B pad)
#define ATILE (128 * PITCH)               // 10240
#define BTILE (64 * PITCH)                // 5120
#define STAGE (ATILE + BTILE)             // 15360
#define GEMM_SMEM (3 * STAGE)             // 46080

template <bool HALF_OUT>
__global__ void __launch_bounds__(256, 3)
gemm_h16_kernel(const __half* __restrict__ X, const __half* __restrict__ Wt,
                const float* __restrict__ bias, void* __restrict__ Cp, int Ntot) {
    extern __shared__ char smem[];
    const uint32_t sbase = smem_u32(smem);

    const int tid  = threadIdx.x;
    const int lane = tid & 31;
    const int warp = tid >> 5;
    const long bm = (long)blockIdx.y * BM;
    const int  bn = blockIdx.x * BN;
    const int wm = (warp >> 1) * 32;     // 4 warps along M, 32 rows each
    const int wn = (warp & 1) * 32;      // 2 warps along N, 32 cols each
    const int qr = lane >> 2;            // 0..7
    const int qc = lane & 3;             // 0..3

    // A (x4 = one m16k16 frag): row = wm + mi*16 + (lane&15), koff = (lane>>4)*16
    const uint32_t aOff = (uint32_t)(wm + (lane & 15)) * PITCH + ((lane >> 4) << 4);
    // B (x4 = two n8k16 frags): row = wn + p*16 + (lane>>4)*8 + (lane&7), koff = ((lane>>3)&1)*16
    const uint32_t bOff = ATILE + (uint32_t)(wn + ((lane >> 4) << 3) + (lane & 7)) * PITCH
                        + (((lane >> 3) & 1) << 4);

    // fill: A rows are Xh[bm+r][k0..k0+32), B rows are Wt[bn+r][k0..k0+32); 64B/row.
    auto fill = [&](int st, int kt) {
        const uint32_t abase = sbase + st * STAGE;
        const uint32_t bbase = abase + ATILE;
        const int k0 = kt * BK;
        const __half* Xb = X + (size_t)bm * CDIM + k0;
        const __half* Wb = Wt + (size_t)bn * CDIM + k0;
#pragma unroll
        for (int j = 0; j < 2; j++) {          // A: 128 rows x 4 chunks = 512 chunks
            const int id  = tid + 256 * j;
            const int row = id >> 2;
            const int c   = id & 3;
            cp16(abase + row * PITCH + c * 16, Xb + (size_t)row * CDIM + c * 8);
        }
        {                                       // B: 64 rows x 4 chunks = 256 chunks
            const int row = tid >> 2;
            const int c   = tid & 3;
            cp16(bbase + row * PITCH + c * 16, Wb + (size_t)row * CDIM + c * 8);
        }
    };

    float acc[2][4][4];
#pragma unroll
    for (int mi = 0; mi < 2; mi++)
#pragma unroll
        for (int ni = 0; ni < 4; ni++)
#pragma unroll
            for (int r = 0; r < 4; r++) acc[mi][ni][r] = 0.f;

    fill(0, 0); CP_COMMIT();
    fill(1, 1); CP_COMMIT();

    const int NKT = CDIM / BK;   // 16
    for (int kt = 0; kt < NKT; kt++) {
        CP_WAIT1();
        __syncthreads();
        if (kt + 2 < NKT) fill((kt + 2) % 3, kt + 2);
        CP_COMMIT();

        const uint32_t stb = sbase + (kt % 3) * STAGE;
        const uint32_t aAddr = stb + aOff;
        const uint32_t bAddr = stb + bOff;

#pragma unroll
        for (int ks = 0; ks < 2; ks++) {           // two k16 slices per BK=32
            const uint32_t kb = ks * 32;
            uint32_t afr[2][4];
#pragma unroll
            for (int mi = 0; mi < 2; mi++)
                ldsm_x4(afr[mi][0], afr[mi][1], afr[mi][2], afr[mi][3],
                        aAddr + mi * (16 * PITCH) + kb);
            uint32_t bfr[4][2];
#pragma unroll
            for (int p = 0; p < 2; p++)
                ldsm_x4(bfr[2 * p][0], bfr[2 * p][1], bfr[2 * p + 1][0], bfr[2 * p + 1][1],
                        bAddr + p * (16 * PITCH) + kb);
#pragma unroll
            for (int mi = 0; mi < 2; mi++)
#pragma unroll
                for (int ni = 0; ni < 4; ni++)
                    mma_f16(acc[mi][ni], afr[mi][0], afr[mi][1], afr[mi][2], afr[mi][3],
                            bfr[ni][0], bfr[ni][1]);
        }
    }

    // epilogue: add bias, store (fp16 or fp32)
#pragma unroll
    for (int mi = 0; mi < 2; mi++) {
        const long row = bm + wm + mi * 16 + qr;
#pragma unroll
        for (int ni = 0; ni < 4; ni++) {
            const int col = bn + wn + ni * 8 + (qc << 1);
            const float b0v = __ldg(bias + col), b1v = __ldg(bias + col + 1);
            if (HALF_OUT) {
                __half* C = (__half*)Cp;
                *(__half2*)(C + (size_t)row * Ntot + col) =
                    __floats2half2_rn(acc[mi][ni][0] + b0v, acc[mi][ni][1] + b1v);
                *(__half2*)(C + (size_t)(row + 8) * Ntot + col) =
                    __floats2half2_rn(acc[mi][ni][2] + b0v, acc[mi][ni][3] + b1v);
            } else {
                float* C = (float*)Cp;
                *(float2*)(C + (size_t)row * Ntot + col) =
                    make_float2(acc[mi][ni][0] + b0v, acc[mi][ni][1] + b1v);
                *(float2*)(C + (size_t)(row + 8) * Ntot + col) =
                    make_float2(acc[mi][ni][2] + b0v, acc[mi][ni][3] + b1v);
            }
        }
    }
}

// ---------------- attention (R11 proven version): one CTA per (window, head), 4 warps ----
// Reads fp16 qkv (fp16 -> fp32 exact; fp16 mantissa fits tf32). Writes fp16 attn-out.
__global__ void __launch_bounds__(128)
attn_kernel(const __half* __restrict__ qkv, const float* __restrict__ mask,
            const float* __restrict__ biasg, __half* __restrict__ outp) {
    __shared__ uint32_t qs[64][36];
    __shared__ uint32_t ksm[64][36];
    __shared__ uint32_t vsm[64][40];
    __shared__ uint32_t ps[4][16][68];
    __shared__ float    masks[64];

    const int b = blockIdx.x;
    const int h = blockIdx.y;
    const int tid  = threadIdx.x;
    const int lane = tid & 31;
    const int warp = tid >> 5;
    const int qr = lane >> 2;   // 0..7
    const int qc = lane & 3;    // 0..3

    const __half* base = qkv + (size_t)b * NTOK * NQKV + h * DHEAD;
#pragma unroll
    for (int p = 0; p < 4; p++) {
        const int g = tid + 128 * p;
        const int t = g >> 3;
        const int c = (g & 7) << 2;
        const __half* rowp = base + (size_t)t * NQKV + c;
#pragma unroll
        for (int s = 0; s < 3; s++) {
            const __half2 v01 = *(const __half2*)(rowp + s * CDIM);
            const __half2 v23 = *(const __half2*)(rowp + s * CDIM + 2);
            const float2 f01 = __half22float2(v01);
            const float2 f23 = __half22float2(v23);
            uint32_t* dst = (s == 0) ? &qs[t][c] : (s == 1) ? &ksm[t][c] : &vsm[t][c];
            dst[0] = __float_as_uint(f01.x); dst[1] = __float_as_uint(f01.y);
            dst[2] = __float_as_uint(f23.x); dst[3] = __float_as_uint(f23.y);
        }
    }
    if (tid < 64) masks[tid] = mask[(size_t)b * NTOK + tid];
    __syncthreads();

    const int i0 = warp * 16;
    float sacc[8][4];
#pragma unroll
    for (int nt = 0; nt < 8; nt++)
#pragma unroll
        for (int r = 0; r < 4; r++) sacc[nt][r] = 0.f;

#pragma unroll
    for (int ks = 0; ks < 4; ks++) {
        const int c = ks * 8 + qc;
        const uint32_t a0 = qs[i0 + qr][c];
        const uint32_t a1 = qs[i0 + 8 + qr][c];
        const uint32_t a2 = qs[i0 + qr][c + 4];
        const uint32_t a3 = qs[i0 + 8 + qr][c + 4];
#pragma unroll
        for (int nt = 0; nt < 8; nt++) {
            const uint32_t b0 = ksm[nt * 8 + qr][c];
            const uint32_t b1 = ksm[nt * 8 + qr][c + 4];
            mma_tf32(sacc[nt], a0, a1, a2, a3, b0, b1);
        }
    }

    const float scale = 0.17677669529663687f;   // 1/sqrt(32)
    const float* brow = biasg + h * (NTOK * NTOK);
    const int ra = i0 + qr;
    const int rb = ra + 8;

    float pv[8][4];
    float mA = -1e30f, mB = -1e30f;
#pragma unroll
    for (int nt = 0; nt < 8; nt++) {
        const int j = nt * 8 + (qc << 1);
        const float2 biA = *(const float2*)(brow + ra * 64 + j);
        const float2 biB = *(const float2*)(brow + rb * 64 + j);
        const float m0 = masks[j], m1 = masks[j + 1];
        pv[nt][0] = sacc[nt][0] * scale + biA.x + m0;
        pv[nt][1] = sacc[nt][1] * scale + biA.y + m1;
        pv[nt][2] = sacc[nt][2] * scale + biB.x + m0;
        pv[nt][3] = sacc[nt][3] * scale + biB.y + m1;
        mA = fmaxf(mA, fmaxf(pv[nt][0], pv[nt][1]));
        mB = fmaxf(mB, fmaxf(pv[nt][2], pv[nt][3]));
    }
#pragma unroll
    for (int off = 1; off <= 2; off <<= 1) {
        mA = fmaxf(mA, __shfl_xor_sync(0xffffffffu, mA, off));
        mB = fmaxf(mB, __shfl_xor_sync(0xffffffffu, mB, off));
    }
    float sA = 0.f, sB = 0.f;
#pragma unroll
    for (int nt = 0; nt < 8; nt++) {
        pv[nt][0] = __expf(pv[nt][0] - mA);
        pv[nt][1] = __expf(pv[nt][1] - mA);
        pv[nt][2] = __expf(pv[nt][2] - mB);
        pv[nt][3] = __expf(pv[nt][3] - mB);
        sA += pv[nt][0] + pv[nt][1];
        sB += pv[nt][2] + pv[nt][3];
    }
#pragma unroll
    for (int off = 1; off <= 2; off <<= 1) {
        sA += __shfl_xor_sync(0xffffffffu, sA, off);
        sB += __shfl_xor_sync(0xffffffffu, sB, off);
    }
    const float rAi = 1.f / sA;
    const float rBi = 1.f / sB;

#pragma unroll
    for (int nt = 0; nt < 8; nt++) {
        const int j = nt * 8 + (qc << 1);
        ps[warp][qr][j]         = f2tf32(pv[nt][0] * rAi);
        ps[warp][qr][j + 1]     = f2tf32(pv[nt][1] * rAi);
        ps[warp][qr + 8][j]     = f2tf32(pv[nt][2] * rBi);
        ps[warp][qr + 8][j + 1] = f2tf32(pv[nt][3] * rBi);
    }
    __syncwarp();

    float oacc[4][4];
#pragma unroll
    for (int nt = 0; nt < 4; nt++)
#pragma unroll
        for (int r = 0; r < 4; r++) oacc[nt][r] = 0.f;

#pragma unroll
    for (int ks = 0; ks < 8; ks++) {
        const int c = ks * 8 + qc;
        const uint32_t a0 = ps[warp][qr][c];
        const uint32_t a1 = ps[warp][qr + 8][c];
        const uint32_t a2 = ps[warp][qr][c + 4];
        const uint32_t a3 = ps[warp][qr + 8][c + 4];
#pragma unroll
        for (int nt = 0; nt < 4; nt++) {
            const uint32_t b0 = vsm[ks * 8 + qc][nt * 8 + qr];
            const uint32_t b1 = vsm[ks * 8 + 4 + qc][nt * 8 + qr];
            mma_tf32(oacc[nt], a0, a1, a2, a3, b0, b1);
        }
    }

    __half* ob = outp + ((size_t)b * NTOK + i0) * CDIM + h * DHEAD;
#pragma unroll
    for (int nt = 0; nt < 4; nt++) {
        const int d = nt * 8 + (qc << 1);
        *(__half2*)(ob + (size_t)qr * CDIM + d) = __floats2half2_rn(oacc[nt][0], oacc[nt][1]);
        *(__half2*)(ob + (size_t)(qr + 8) * CDIM + d) = __floats2half2_rn(oacc[nt][2], oacc[nt][3]);
    }
}

// ---------------- launch ----------------
extern "C" void kernel_launch(void* const* d_in, const int* in_sizes, int n_in,
                              void* d_out, int out_size) {
    const float* x      = (const float*)d_in[0];
    const float* mask   = (const float*)d_in[1];
    const float* qkv_w  = (const float*)d_in[2];
    const float* qkv_b  = (const float*)d_in[3];
    const float* table  = (const float*)d_in[4];
    const float* proj_w = (const float*)d_in[5];
    const float* proj_b = (const float*)d_in[6];
    const int*   relidx = (const int*)d_in[7];
    float* out = (float*)d_out;

    __half *p_xh, *p_qkvh, *p_atth, *p_wqkv, *p_wprj;
    float  *p_bias;
    cudaGetSymbolAddress((void**)&p_xh,   g_xh);
    cudaGetSymbolAddress((void**)&p_qkvh, g_qkvh);
    cudaGetSymbolAddress((void**)&p_atth, g_atth);
    cudaGetSymbolAddress((void**)&p_wqkv, g_wqkv);
    cudaGetSymbolAddress((void**)&p_wprj, g_wprj);
    cudaGetSymbolAddress((void**)&p_bias, g_bias);

    cudaFuncSetAttribute(gemm_h16_kernel<true>,
                         cudaFuncAttributeMaxDynamicSharedMemorySize, GEMM_SMEM);
    cudaFuncSetAttribute(gemm_h16_kernel<false>,
                         cudaFuncAttributeMaxDynamicSharedMemorySize, GEMM_SMEM);

    // prep: x -> fp16 ; W -> W^T fp16 ; bias gather
    cvt_half_kernel<<<(size_t)MROWS * CDIM / (256 * 8), 256>>>(x, p_xh);
    wtrans_kernel<<<NQKV * CDIM / 256, 256>>>(qkv_w, p_wqkv, NQKV);
    wtrans_kernel<<<CDIM * CDIM / 256, 256>>>(proj_w, p_wprj, CDIM);
    bias_kernel<<<HEADS, 256>>>(table, relidx, p_bias);

    // QKV projection: [262144, 512] @ [512, 1536] + b -> fp16
    gemm_h16_kernel<true><<<dim3(NQKV / BN, MROWS / BM), 256, GEMM_SMEM>>>(
        p_xh, p_wqkv, qkv_b, p_qkvh, NQKV);

    // windowed attention per (window, head) -> fp16
    attn_kernel<<<dim3(NW, HEADS), 128>>>(p_qkvh, mask, p_bias, p_atth);

    // output projection: [262144, 512] @ [512, 512] + b -> fp32
    gemm_h16_kernel<false><<<dim3(CDIM / BN, MROWS / BM), 256, GEMM_SMEM>>>(
        p_atth, p_wprj, proj_b, out, CDIM);
}

// round 16
// speedup vs baseline: 1.1167x; 1.1167x over previous
#include <cuda_runtime.h>
#include <cuda_fp16.h>
#include <cstdint>

// ---------------- problem constants ----------------
#define NW    4096
#define NTOK  64
#define CDIM  512
#define HEADS 16
#define DHEAD 32
#define MROWS (NW * NTOK)        // 262144
#define NQKV  (3 * CDIM)         // 1536

// ---------------- scratch (device globals; no allocs allowed) ----------------
__device__ __half g_xh  [(size_t)MROWS * CDIM];   // 256 MB  x in fp16
__device__ __half g_qkvh[(size_t)MROWS * NQKV];   // 768 MB  qkv in fp16
__device__ __half g_atth[(size_t)MROWS * CDIM];   // 256 MB  attn out in fp16
__device__ __half g_wqkv[(size_t)NQKV * CDIM];    // 1.5 MB  qkv_w^T fp16 [n][k]
__device__ __half g_wprj[(size_t)CDIM * CDIM];    // 0.5 MB  proj_w^T fp16 [n][k]
__device__ float  g_bias[HEADS * NTOK * NTOK];    // 256 KB

// ---------------- helpers ----------------
__device__ __forceinline__ void mma_tf32(float d[4],
                                         uint32_t a0, uint32_t a1, uint32_t a2, uint32_t a3,
                                         uint32_t b0, uint32_t b1) {
    asm volatile(
        "mma.sync.aligned.m16n8k8.row.col.f32.tf32.tf32.f32 "
        "{%0,%1,%2,%3}, {%4,%5,%6,%7}, {%8,%9}, {%0,%1,%2,%3};\n"
        : "+f"(d[0]), "+f"(d[1]), "+f"(d[2]), "+f"(d[3])
        : "r"(a0), "r"(a1), "r"(a2), "r"(a3), "r"(b0), "r"(b1));
}
__device__ __forceinline__ void mma_f16(float d[4],
                                        uint32_t a0, uint32_t a1, uint32_t a2, uint32_t a3,
                                        uint32_t b0, uint32_t b1) {
    asm volatile(
        "mma.sync.aligned.m16n8k16.row.col.f32.f16.f16.f32 "
        "{%0,%1,%2,%3}, {%4,%5,%6,%7}, {%8,%9}, {%0,%1,%2,%3};\n"
        : "+f"(d[0]), "+f"(d[1]), "+f"(d[2]), "+f"(d[3])
        : "r"(a0), "r"(a1), "r"(a2), "r"(a3), "r"(b0), "r"(b1));
}
__device__ __forceinline__ void ldsm_x4(uint32_t& r0, uint32_t& r1, uint32_t& r2, uint32_t& r3,
                                        uint32_t addr) {
    asm volatile("ldmatrix.sync.aligned.m8n8.x4.shared.b16 {%0,%1,%2,%3}, [%4];"
                 : "=r"(r0), "=r"(r1), "=r"(r2), "=r"(r3) : "r"(addr));
}
__device__ __forceinline__ uint32_t f2tf32(float x) {
    uint32_t r;
    asm("cvt.rna.tf32.f32 %0, %1;" : "=r"(r) : "f"(x));
    return r;
}
__device__ __forceinline__ uint32_t smem_u32(const void* p) {
    uint32_t a;
    asm("{ .reg .u64 t; cvta.to.shared.u64 t, %1; cvt.u32.u64 %0, t; }" : "=r"(a) : "l"(p));
    return a;
}
__device__ __forceinline__ void cp16(uint32_t dst, const void* src) {
    asm volatile("cp.async.cg.shared.global [%0], [%1], 16;\n" :: "r"(dst), "l"(src));
}
#define CP_COMMIT() asm volatile("cp.async.commit_group;\n" ::: "memory")
#define CP_WAIT1()  asm volatile("cp.async.wait_group 1;\n" ::: "memory")

// ---------------- fused prep: x->fp16 | qkv_w^T fp16 | proj_w^T fp16 | bias gather -----
// grid layout: [0, 65536)            cvt_half   (8 elems/thread)
//              [65536, 65536+3072)   wtrans qkv (1536x512)
//              [68608, 68608+1024)   wtrans proj (512x512)
//              [69632, 69632+16)     bias gather (16 heads)
#define PREP_CVT_BLOCKS    65536
#define PREP_WQKV_BLOCKS   3072
#define PREP_WPRJ_BLOCKS   1024
#define PREP_BIAS_BLOCKS   16
#define PREP_BLOCKS (PREP_CVT_BLOCKS + PREP_WQKV_BLOCKS + PREP_WPRJ_BLOCKS + PREP_BIAS_BLOCKS)

__global__ void prep_kernel(const float* __restrict__ x,
                            const float* __restrict__ qkv_w,
                            const float* __restrict__ proj_w,
                            const float* __restrict__ table,
                            const int* __restrict__ relidx,
                            __half* __restrict__ xh,
                            __half* __restrict__ wqkv,
                            __half* __restrict__ wprj,
                            float* __restrict__ bias_out) {
    const int blk = blockIdx.x;
    if (blk < PREP_CVT_BLOCKS) {
        const size_t base = ((size_t)blk * blockDim.x + threadIdx.x) * 8;
        float4 a = *(const float4*)(x + base);
        float4 b = *(const float4*)(x + base + 4);
        __half2 h0 = __floats2half2_rn(a.x, a.y);
        __half2 h1 = __floats2half2_rn(a.z, a.w);
        __half2 h2 = __floats2half2_rn(b.x, b.y);
        __half2 h3 = __floats2half2_rn(b.z, b.w);
        uint4 o;
        o.x = *(uint32_t*)&h0; o.y = *(uint32_t*)&h1;
        o.z = *(uint32_t*)&h2; o.w = *(uint32_t*)&h3;
        *(uint4*)(xh + base) = o;
    } else if (blk < PREP_CVT_BLOCKS + PREP_WQKV_BLOCKS) {
        const int idx = (blk - PREP_CVT_BLOCKS) * blockDim.x + threadIdx.x;  // over 1536*512
        const int n = idx >> 9;
        const int k = idx & 511;
        wqkv[idx] = __float2half_rn(qkv_w[(size_t)k * NQKV + n]);
    } else if (blk < PREP_CVT_BLOCKS + PREP_WQKV_BLOCKS + PREP_WPRJ_BLOCKS) {
        const int idx = (blk - PREP_CVT_BLOCKS - PREP_WQKV_BLOCKS) * blockDim.x + threadIdx.x;
        const int n = idx >> 9;
        const int k = idx & 511;
        wprj[idx] = __float2half_rn(proj_w[(size_t)k * CDIM + n]);
    } else {
        const int h = blk - PREP_CVT_BLOCKS - PREP_WQKV_BLOCKS - PREP_WPRJ_BLOCKS;
        for (int idx = threadIdx.x; idx < NTOK * NTOK; idx += blockDim.x) {
            bias_out[h * (NTOK * NTOK) + idx] = table[relidx[idx] * HEADS + h];
        }
    }
}

// ---------------- fp16 GEMM: C[M,N] = Xh[M,512] @ Wt[N,512]^T + bias[N] ----------------
// CTA 128x128, 8 warps 2(M)x4(N), warp tile 64x32, 2 CTAs/SM, 3-stage cp.async.
// BK=64 (8 pipeline boundaries). fp16 SMEM pitch 144B; ldmatrix fragments.
#define BM 128
#define BN 128
#define BK 64
#define PITCH 144                         // bytes per row (128B data + 16B pad)
#define TILEB (128 * PITCH)               // 18432
#define STAGE (2 * TILEB)                 // 36864 (A + B)
#define GEMM_SMEM (3 * STAGE)             // 110592

template <bool HALF_OUT>
__global__ void __launch_bounds__(256, 2)
gemm_h16_kernel(const __half* __restrict__ X, const __half* __restrict__ Wt,
                const float* __restrict__ bias, void* __restrict__ Cp, int Ntot) {
    extern __shared__ char smem[];
    const uint32_t sbase = smem_u32(smem);

    const int tid  = threadIdx.x;
    const int lane = tid & 31;
    const int warp = tid >> 5;
    const long bm = (long)blockIdx.y * BM;
    const int  bn = blockIdx.x * BN;
    const int wm = (warp >> 2) * 64;     // 2 warps along M
    const int wn = (warp & 3) * 32;      // 4 warps along N
    const int qr = lane >> 2;            // 0..7
    const int qc = lane & 3;             // 0..3

    // A (x4 = one m16k16 frag): row = wm + mi*16 + (lane&15), koff = (lane>>4)*16
    const uint32_t aOff = (uint32_t)(wm + (lane & 15)) * PITCH + ((lane >> 4) << 4);
    // B (x4 = two n8k16 frags): row = wn + p*16 + (lane>>4)*8 + (lane&7), koff = ((lane>>3)&1)*16
    const uint32_t bOff = TILEB + (uint32_t)(wn + ((lane >> 4) << 3) + (lane & 7)) * PITCH
                        + (((lane >> 3) & 1) << 4);

    // fill: A rows are Xh[bm+r][k0..k0+64), B rows are Wt[bn+r][k0..k0+64); both 128B/row.
    auto fill = [&](int st, int kt) {
        const uint32_t abase = sbase + st * STAGE;
        const uint32_t bbase = abase + TILEB;
        const int k0 = kt * BK;
        const __half* Xb = X + (size_t)bm * CDIM + k0;
        const __half* Wb = Wt + (size_t)bn * CDIM + k0;
#pragma unroll
        for (int j = 0; j < 4; j++) {          // 128 rows x 8 chunks(16B) = 1024 chunks
            const int id  = tid + 256 * j;
            const int row = id >> 3;
            const int c   = id & 7;
            cp16(abase + row * PITCH + c * 16, Xb + (size_t)row * CDIM + c * 8);
        }
#pragma unroll
        for (int j = 0; j < 4; j++) {
            const int id  = tid + 256 * j;
            const int row = id >> 3;
            const int c   = id & 7;
            cp16(bbase + row * PITCH + c * 16, Wb + (size_t)row * CDIM + c * 8);
        }
    };

    float acc[4][4][4];
#pragma unroll
    for (int mi = 0; mi < 4; mi++)
#pragma unroll
        for (int ni = 0; ni < 4; ni++)
#pragma unroll
            for (int r = 0; r < 4; r++) acc[mi][ni][r] = 0.f;

    fill(0, 0); CP_COMMIT();
    fill(1, 1); CP_COMMIT();

    const int NKT = CDIM / BK;   // 8
    for (int kt = 0; kt < NKT; kt++) {
        CP_WAIT1();
        __syncthreads();
        if (kt + 2 < NKT) fill((kt + 2) % 3, kt + 2);
        CP_COMMIT();

        const uint32_t stb = sbase + (kt % 3) * STAGE;
        const uint32_t aAddr = stb + aOff;
        const uint32_t bAddr = stb + bOff;

#pragma unroll
        for (int ks = 0; ks < 4; ks++) {           // four k16 slices per BK=64
            const uint32_t kb = ks * 32;
            uint32_t afr[4][4];
#pragma unroll
            for (int mi = 0; mi < 4; mi++)
                ldsm_x4(afr[mi][0], afr[mi][1], afr[mi][2], afr[mi][3],
                        aAddr + mi * (16 * PITCH) + kb);
            uint32_t bfr[4][2];
#pragma unroll
            for (int p = 0; p < 2; p++)
                ldsm_x4(bfr[2 * p][0], bfr[2 * p][1], bfr[2 * p + 1][0], bfr[2 * p + 1][1],
                        bAddr + p * (16 * PITCH) + kb);
#pragma unroll
            for (int mi = 0; mi < 4; mi++)
#pragma unroll
                for (int ni = 0; ni < 4; ni++)
                    mma_f16(acc[mi][ni], afr[mi][0], afr[mi][1], afr[mi][2], afr[mi][3],
                            bfr[ni][0], bfr[ni][1]);
        }
    }

    // epilogue: add bias, store (fp16 or fp32)
#pragma unroll
    for (int mi = 0; mi < 4; mi++) {
        const long row = bm + wm + mi * 16 + qr;
#pragma unroll
        for (int ni = 0; ni < 4; ni++) {
            const int col = bn + wn + ni * 8 + (qc << 1);
            const float b0v = __ldg(bias + col), b1v = __ldg(bias + col + 1);
            if (HALF_OUT) {
                __half* C = (__half*)Cp;
                *(__half2*)(C + (size_t)row * Ntot + col) =
                    __floats2half2_rn(acc[mi][ni][0] + b0v, acc[mi][ni][1] + b1v);
                *(__half2*)(C + (size_t)(row + 8) * Ntot + col) =
                    __floats2half2_rn(acc[mi][ni][2] + b0v, acc[mi][ni][3] + b1v);
            } else {
                float* C = (float*)Cp;
                *(float2*)(C + (size_t)row * Ntot + col) =
                    make_float2(acc[mi][ni][0] + b0v, acc[mi][ni][1] + b1v);
                *(float2*)(C + (size_t)(row + 8) * Ntot + col) =
                    make_float2(acc[mi][ni][2] + b0v, acc[mi][ni][3] + b1v);
            }
        }
    }
}

// ---------------- attention (R11 proven version): one CTA per (window, head), 4 warps ----
// Reads fp16 qkv (fp16 -> fp32 exact; fp16 mantissa fits tf32). Writes fp16 attn-out.
__global__ void __launch_bounds__(128)
attn_kernel(const __half* __restrict__ qkv, const float* __restrict__ mask,
            const float* __restrict__ biasg, __half* __restrict__ outp) {
    __shared__ uint32_t qs[64][36];
    __shared__ uint32_t ksm[64][36];
    __shared__ uint32_t vsm[64][40];
    __shared__ uint32_t ps[4][16][68];
    __shared__ float    masks[64];

    const int b = blockIdx.x;
    const int h = blockIdx.y;
    const int tid  = threadIdx.x;
    const int lane = tid & 31;
    const int warp = tid >> 5;
    const int qr = lane >> 2;   // 0..7
    const int qc = lane & 3;    // 0..3

    const __half* base = qkv + (size_t)b * NTOK * NQKV + h * DHEAD;
#pragma unroll
    for (int p = 0; p < 4; p++) {
        const int g = tid + 128 * p;
        const int t = g >> 3;
        const int c = (g & 7) << 2;
        const __half* rowp = base + (size_t)t * NQKV + c;
#pragma unroll
        for (int s = 0; s < 3; s++) {
            const __half2 v01 = *(const __half2*)(rowp + s * CDIM);
            const __half2 v23 = *(const __half2*)(rowp + s * CDIM + 2);
            const float2 f01 = __half22float2(v01);
            const float2 f23 = __half22float2(v23);
            uint32_t* dst = (s == 0) ? &qs[t][c] : (s == 1) ? &ksm[t][c] : &vsm[t][c];
            dst[0] = __float_as_uint(f01.x); dst[1] = __float_as_uint(f01.y);
            dst[2] = __float_as_uint(f23.x); dst[3] = __float_as_uint(f23.y);
        }
    }
    if (tid < 64) masks[tid] = mask[(size_t)b * NTOK + tid];
    __syncthreads();

    const int i0 = warp * 16;
    float sacc[8][4];
#pragma unroll
    for (int nt = 0; nt < 8; nt++)
#pragma unroll
        for (int r = 0; r < 4; r++) sacc[nt][r] = 0.f;

#pragma unroll
    for (int ks = 0; ks < 4; ks++) {
        const int c = ks * 8 + qc;
        const uint32_t a0 = qs[i0 + qr][c];
        const uint32_t a1 = qs[i0 + 8 + qr][c];
        const uint32_t a2 = qs[i0 + qr][c + 4];
        const uint32_t a3 = qs[i0 + 8 + qr][c + 4];
#pragma unroll
        for (int nt = 0; nt < 8; nt++) {
            const uint32_t b0 = ksm[nt * 8 + qr][c];
            const uint32_t b1 = ksm[nt * 8 + qr][c + 4];
            mma_tf32(sacc[nt], a0, a1, a2, a3, b0, b1);
        }
    }

    const float scale = 0.17677669529663687f;   // 1/sqrt(32)
    const float* brow = biasg + h * (NTOK * NTOK);
    const int ra = i0 + qr;
    const int rb = ra + 8;

    float pv[8][4];
    float mA = -1e30f, mB = -1e30f;
#pragma unroll
    for (int nt = 0; nt < 8; nt++) {
        const int j = nt * 8 + (qc << 1);
        const float2 biA = *(const float2*)(brow + ra * 64 + j);
        const float2 biB = *(const float2*)(brow + rb * 64 + j);
        const float m0 = masks[j], m1 = masks[j + 1];
        pv[nt][0] = sacc[nt][0] * scale + biA.x + m0;
        pv[nt][1] = sacc[nt][1] * scale + biA.y + m1;
        pv[nt][2] = sacc[nt][2] * scale + biB.x + m0;
        pv[nt][3] = sacc[nt][3] * scale + biB.y + m1;
        mA = fmaxf(mA, fmaxf(pv[nt][0], pv[nt][1]));
        mB = fmaxf(mB, fmaxf(pv[nt][2], pv[nt][3]));
    }
#pragma unroll
    for (int off = 1; off <= 2; off <<= 1) {
        mA = fmaxf(mA, __shfl_xor_sync(0xffffffffu, mA, off));
        mB = fmaxf(mB, __shfl_xor_sync(0xffffffffu, mB, off));
    }
    float sA = 0.f, sB = 0.f;
#pragma unroll
    for (int nt = 0; nt < 8; nt++) {
        pv[nt][0] = __expf(pv[nt][0] - mA);
        pv[nt][1] = __expf(pv[nt][1] - mA);
        pv[nt][2] = __expf(pv[nt][2] - mB);
        pv[nt][3] = __expf(pv[nt][3] - mB);
        sA += pv[nt][0] + pv[nt][1];
        sB += pv[nt][2] + pv[nt][3];
    }
#pragma unroll
    for (int off = 1; off <= 2; off <<= 1) {
        sA += __shfl_xor_sync(0xffffffffu, sA, off);
        sB += __shfl_xor_sync(0xffffffffu, sB, off);
    }
    const float rAi = 1.f / sA;
    const float rBi = 1.f / sB;

#pragma unroll
    for (int nt = 0; nt < 8; nt++) {
        const int j = nt * 8 + (qc << 1);
        ps[warp][qr][j]         = f2tf32(pv[nt][0] * rAi);
        ps[warp][qr][j + 1]     = f2tf32(pv[nt][1] * rAi);
        ps[warp][qr + 8][j]     = f2tf32(pv[nt][2] * rBi);
        ps[warp][qr + 8][j + 1] = f2tf32(pv[nt][3] * rBi);
    }
    __syncwarp();

    float oacc[4][4];
#pragma unroll
    for (int nt = 0; nt < 4; nt++)
#pragma unroll
        for (int r = 0; r < 4; r++) oacc[nt][r] = 0.f;

#pragma unroll
    for (int ks = 0; ks < 8; ks++) {
        const int c = ks * 8 + qc;
        const uint32_t a0 = ps[warp][qr][c];
        const uint32_t a1 = ps[warp][qr + 8][c];
        const uint32_t a2 = ps[warp][qr][c + 4];
        const uint32_t a3 = ps[warp][qr + 8][c + 4];
#pragma unroll
        for (int nt = 0; nt < 4; nt++) {
            const uint32_t b0 = vsm[ks * 8 + qc][nt * 8 + qr];
            const uint32_t b1 = vsm[ks * 8 + 4 + qc][nt * 8 + qr];
            mma_tf32(oacc[nt], a0, a1, a2, a3, b0, b1);
        }
    }

    __half* ob = outp + ((size_t)b * NTOK + i0) * CDIM + h * DHEAD;
#pragma unroll
    for (int nt = 0; nt < 4; nt++) {
        const int d = nt * 8 + (qc << 1);
        *(__half2*)(ob + (size_t)qr * CDIM + d) = __floats2half2_rn(oacc[nt][0], oacc[nt][1]);
        *(__half2*)(ob + (size_t)(qr + 8) * CDIM + d) = __floats2half2_rn(oacc[nt][2], oacc[nt][3]);
    }
}

// ---------------- launch ----------------
extern "C" void kernel_launch(void* const* d_in, const int* in_sizes, int n_in,
                              void* d_out, int out_size) {
    const float* x      = (const float*)d_in[0];
    const float* mask   = (const float*)d_in[1];
    const float* qkv_w  = (const float*)d_in[2];
    const float* qkv_b  = (const float*)d_in[3];
    const float* table  = (const float*)d_in[4];
    const float* proj_w = (const float*)d_in[5];
    const float* proj_b = (const float*)d_in[6];
    const int*   relidx = (const int*)d_in[7];
    float* out = (float*)d_out;

    __half *p_xh, *p_qkvh, *p_atth, *p_wqkv, *p_wprj;
    float  *p_bias;
    cudaGetSymbolAddress((void**)&p_xh,   g_xh);
    cudaGetSymbolAddress((void**)&p_qkvh, g_qkvh);
    cudaGetSymbolAddress((void**)&p_atth, g_atth);
    cudaGetSymbolAddress((void**)&p_wqkv, g_wqkv);
    cudaGetSymbolAddress((void**)&p_wprj, g_wprj);
    cudaGetSymbolAddress((void**)&p_bias, g_bias);

    cudaFuncSetAttribute(gemm_h16_kernel<true>,
                         cudaFuncAttributeMaxDynamicSharedMemorySize, GEMM_SMEM);
    cudaFuncSetAttribute(gemm_h16_kernel<false>,
                         cudaFuncAttributeMaxDynamicSharedMemorySize, GEMM_SMEM);

    // fused prep: x -> fp16 ; W -> W^T fp16 ; bias gather (one launch)
    prep_kernel<<<PREP_BLOCKS, 256>>>(x, qkv_w, proj_w, table, relidx,
                                      p_xh, p_wqkv, p_wprj, p_bias);

    // QKV projection: [262144, 512] @ [512, 1536] + b -> fp16
    gemm_h16_kernel<true><<<dim3(NQKV / BN, MROWS / BM), 256, GEMM_SMEM>>>(
        p_xh, p_wqkv, qkv_b, p_qkvh, NQKV);

    // windowed attention per (window, head) -> fp16
    attn_kernel<<<dim3(NW, HEADS), 128>>>(p_qkvh, mask, p_bias, p_atth);

    // output projection: [262144, 512] @ [512, 512] + b -> fp32
    gemm_h16_kernel<false><<<dim3(CDIM / BN, MROWS / BM), 256, GEMM_SMEM>>>(
        p_atth, p_wprj, proj_b, out, CDIM);
}